// round 16
// baseline (speedup 1.0000x reference)
#include <cuda_runtime.h>
#include <mma.h>
#include <cuda_fp16.h>
#include <cstdint>

using namespace nvcuda;

#define SQ   512
#define BB   4
#define DIN_ 768
#define DD   1024
#define HH   16
#define HDIM 64
#define FF_  4096
#define MROWS 2048   // S*B
#define LAYERS 12

// ---------------- device scratch (no allocs allowed) ----------------
__device__ float g_x   [MROWS*DD];
__device__ float g_h   [MROWS*DD];
__device__ float g_q   [MROWS*DD];
__device__ float g_k   [MROWS*DD];
__device__ float g_v   [MROWS*DD];
__device__ float g_attn[MROWS*DD];
__device__ float g_ffh [MROWS*FF_];
__device__ float g_rope[SQ*32*2];   // interleaved cos,sin per (s, j<32)
__device__ int   g_mask[BB*SQ];     // canonical 0/1 key mask

// ---------------- mask canonicalization (bool / int32 / float32 robust) ----
__global__ void k_mask_prep(const unsigned char* __restrict__ raw,
                            int* __restrict__ outm){
    __shared__ int s_float, s_bool;
    if (threadIdx.x==0){ s_float=0; s_bool=0; }
    __syncthreads();
    for (int i=threadIdx.x; i<BB*SQ; i+=256){
        unsigned char v = raw[i];
        if ((i&3)==3 && v==0x3f) atomicOr(&s_float,1);   // 1.0f byte pattern
        else if ((i&3)!=0 && v!=0) atomicOr(&s_bool,1);  // random bools
    }
    __syncthreads();
    int mode = s_float ? 2 : (s_bool ? 0 : 1); // 0=bool, 1=int32, 2=float32
    for (int i=threadIdx.x; i<BB*SQ; i+=256){
        int m;
        if (mode==0)      m = raw[i] != 0;
        else if (mode==1) m = ((const int*)raw)[i] != 0;
        else              m = ((const float*)raw)[i] != 0.f;
        outm[i] = m;
    }
}

// ---------------- RoPE cache ----------------
__global__ void k_rope_cache(float* __restrict__ cache){
    int i = blockIdx.x*blockDim.x + threadIdx.x;
    if (i >= SQ*32) return;
    int s = i >> 5, j = i & 31;
    float invf = powf(10000.f, -((float)(2*j)) / 64.f);
    float a = (float)s * invf;
    cache[2*i]   = cosf(a);
    cache[2*i+1] = sinf(a);
}

// ---------------- LayerNorm ----------------
__global__ __launch_bounds__(256) void k_ln(const float* __restrict__ x,
                                            const float* __restrict__ g,
                                            const float* __restrict__ b,
                                            float* __restrict__ out){
    int row = blockIdx.x, tid = threadIdx.x;
    const float4* xr = (const float4*)(x + (size_t)row*DD);
    float4 v = xr[tid];
    float s  = v.x+v.y+v.z+v.w;
    float q2 = v.x*v.x+v.y*v.y+v.z*v.z+v.w*v.w;
    #pragma unroll
    for (int o=16;o;o>>=1){ s += __shfl_xor_sync(0xffffffffu,s,o);
                            q2 += __shfl_xor_sync(0xffffffffu,q2,o); }
    __shared__ float ss[8], sq[8];
    if ((tid&31)==0){ ss[tid>>5]=s; sq[tid>>5]=q2; }
    __syncthreads();
    float S_=0.f, Q_=0.f;
    #pragma unroll
    for (int i=0;i<8;i++){ S_+=ss[i]; Q_+=sq[i]; }
    float mean = S_ * (1.f/DD);
    float var  = Q_ * (1.f/DD) - mean*mean;
    float inv  = rsqrtf(var + 1e-5f);
    float4 gg = ((const float4*)g)[tid];
    float4 bb = ((const float4*)b)[tid];
    float4 o4;
    o4.x = (v.x-mean)*inv*gg.x + bb.x;
    o4.y = (v.y-mean)*inv*gg.y + bb.y;
    o4.z = (v.z-mean)*inv*gg.z + bb.z;
    o4.w = (v.w-mean)*inv*gg.w + bb.w;
    ((float4*)(out + (size_t)row*DD))[tid] = o4;
}

// split helper: v = hi + lo with hi = fp16(v), lo = fp16(v - hi)
__device__ __forceinline__ void h_split(float v, half& hi, half& lo){
    hi = __float2half_rn(v);
    lo = __float2half_rn(v - __half2float(hi));
}

// ======================================================================
// 3xFP16-split GEMM, double-buffered. C = epi(A[M,K] @ W[K,N])
// CTA tile 128x128, BK=16, 8 warps (4x2), warp tile 32x64.
// ======================================================================
#define GA  24
#define GBN 136
#define STAGEH 10496

__global__ __launch_bounds__(256,1) void k_gemm(
    const float* __restrict__ A, int lda,
    const float* __restrict__ W,
    const float* __restrict__ bias,
    const float* __restrict__ residual,
    const float* __restrict__ rowscale,   // durations (per-row scalar) or null
    const float* __restrict__ colvec,     // Wdur
    const float* __restrict__ colbias,    // bdur
    float* __restrict__ C,
    int N, int K, int gelu)
{
    __shared__ __align__(16) unsigned char smraw[41984];
    half*  hs = (half*)smraw;
    float* fs = (float*)smraw;

    int tid = threadIdx.x, wid = tid>>5, lid = tid&31;
    int wm = wid & 3, wn = wid >> 2;
    int tile_n = blockIdx.x*128, tile_m = blockIdx.y*128;

    int ar0 = tid>>2,  ac = (tid&3)*4;      // A: 2 float4/thread
    int ar1 = ar0 + 64;
    int br  = tid>>4;  int bc = (tid&15)*4; // B: 2 float4/thread (cols bc, bc+64)

    const float* Arow0 = A + (size_t)(tile_m+ar0)*lda + ac;
    const float* Arow1 = A + (size_t)(tile_m+ar1)*lda + ac;
    const float* Brow  = W + (size_t)br*N + tile_n + bc;

    wmma::fragment<wmma::accumulator,16,16,16,float> acc[2][4];
    #pragma unroll
    for (int i=0;i<2;i++)
        #pragma unroll
        for (int j=0;j<4;j++) wmma::fill_fragment(acc[i][j], 0.f);

    int nch = K >> 4;
    float4 ra0, ra1, rb0, rb1;

    ra0 = *(const float4*)(Arow0);
    ra1 = *(const float4*)(Arow1);
    rb0 = *(const float4*)(Brow);
    rb1 = *(const float4*)(Brow + 64);
    {
        half* AH = hs;          half* AL = hs + 3072;
        half* BH = hs + 6144;   half* BL = hs + 8320;
        half hi,lo;
        h_split(ra0.x,hi,lo); AH[ar0*GA+ac+0]=hi; AL[ar0*GA+ac+0]=lo;
        h_split(ra0.y,hi,lo); AH[ar0*GA+ac+1]=hi; AL[ar0*GA+ac+1]=lo;
        h_split(ra0.z,hi,lo); AH[ar0*GA+ac+2]=hi; AL[ar0*GA+ac+2]=lo;
        h_split(ra0.w,hi,lo); AH[ar0*GA+ac+3]=hi; AL[ar0*GA+ac+3]=lo;
        h_split(ra1.x,hi,lo); AH[ar1*GA+ac+0]=hi; AL[ar1*GA+ac+0]=lo;
        h_split(ra1.y,hi,lo); AH[ar1*GA+ac+1]=hi; AL[ar1*GA+ac+1]=lo;
        h_split(ra1.z,hi,lo); AH[ar1*GA+ac+2]=hi; AL[ar1*GA+ac+2]=lo;
        h_split(ra1.w,hi,lo); AH[ar1*GA+ac+3]=hi; AL[ar1*GA+ac+3]=lo;
        h_split(rb0.x,hi,lo); BH[br*GBN+bc+0]=hi; BL[br*GBN+bc+0]=lo;
        h_split(rb0.y,hi,lo); BH[br*GBN+bc+1]=hi; BL[br*GBN+bc+1]=lo;
        h_split(rb0.z,hi,lo); BH[br*GBN+bc+2]=hi; BL[br*GBN+bc+2]=lo;
        h_split(rb0.w,hi,lo); BH[br*GBN+bc+3]=hi; BL[br*GBN+bc+3]=lo;
        h_split(rb1.x,hi,lo); BH[br*GBN+bc+64]=hi; BL[br*GBN+bc+64]=lo;
        h_split(rb1.y,hi,lo); BH[br*GBN+bc+65]=hi; BL[br*GBN+bc+65]=lo;
        h_split(rb1.z,hi,lo); BH[br*GBN+bc+66]=hi; BL[br*GBN+bc+66]=lo;
        h_split(rb1.w,hi,lo); BH[br*GBN+bc+67]=hi; BL[br*GBN+bc+67]=lo;
    }
    __syncthreads();

    for (int ch=0; ch<nch; ch++){
        int cur = ch & 1;
        if (ch+1 < nch){
            int k0 = (ch+1)<<4;
            ra0 = *(const float4*)(Arow0 + k0);
            ra1 = *(const float4*)(Arow1 + k0);
            rb0 = *(const float4*)(Brow  + (size_t)k0*N);
            rb1 = *(const float4*)(Brow  + (size_t)k0*N + 64);
        }
        {
            half* AH = hs + cur*STAGEH;
            half* AL = AH + 3072;
            half* BH = AH + 6144;
            half* BL = AH + 8320;
            wmma::fragment<wmma::matrix_a,16,16,16,half,wmma::row_major> ah[2], al[2];
            wmma::fragment<wmma::matrix_b,16,16,16,half,wmma::row_major> bh[4], bl[4];
            #pragma unroll
            for (int i=0;i<2;i++){
                wmma::load_matrix_sync(ah[i], AH + (wm*32+i*16)*GA, GA);
                wmma::load_matrix_sync(al[i], AL + (wm*32+i*16)*GA, GA);
            }
            #pragma unroll
            for (int j=0;j<4;j++){
                wmma::load_matrix_sync(bh[j], BH + wn*64 + j*16, GBN);
                wmma::load_matrix_sync(bl[j], BL + wn*64 + j*16, GBN);
            }
            #pragma unroll
            for (int i=0;i<2;i++)
                #pragma unroll
                for (int j=0;j<4;j++){
                    wmma::mma_sync(acc[i][j], ah[i], bl[j], acc[i][j]);
                    wmma::mma_sync(acc[i][j], al[i], bh[j], acc[i][j]);
                    wmma::mma_sync(acc[i][j], ah[i], bh[j], acc[i][j]);
                }
        }
        if (ch+1 < nch){
            half* AH = hs + (cur^1)*STAGEH;
            half* AL = AH + 3072;
            half* BH = AH + 6144;
            half* BL = AH + 8320;
            half hi,lo;
            h_split(ra0.x,hi,lo); AH[ar0*GA+ac+0]=hi; AL[ar0*GA+ac+0]=lo;
            h_split(ra0.y,hi,lo); AH[ar0*GA+ac+1]=hi; AL[ar0*GA+ac+1]=lo;
            h_split(ra0.z,hi,lo); AH[ar0*GA+ac+2]=hi; AL[ar0*GA+ac+2]=lo;
            h_split(ra0.w,hi,lo); AH[ar0*GA+ac+3]=hi; AL[ar0*GA+ac+3]=lo;
            h_split(ra1.x,hi,lo); AH[ar1*GA+ac+0]=hi; AL[ar1*GA+ac+0]=lo;
            h_split(ra1.y,hi,lo); AH[ar1*GA+ac+1]=hi; AL[ar1*GA+ac+1]=lo;
            h_split(ra1.z,hi,lo); AH[ar1*GA+ac+2]=hi; AL[ar1*GA+ac+2]=lo;
            h_split(ra1.w,hi,lo); AH[ar1*GA+ac+3]=hi; AL[ar1*GA+ac+3]=lo;
            h_split(rb0.x,hi,lo); BH[br*GBN+bc+0]=hi; BL[br*GBN+bc+0]=lo;
            h_split(rb0.y,hi,lo); BH[br*GBN+bc+1]=hi; BL[br*GBN+bc+1]=lo;
            h_split(rb0.z,hi,lo); BH[br*GBN+bc+2]=hi; BL[br*GBN+bc+2]=lo;
            h_split(rb0.w,hi,lo); BH[br*GBN+bc+3]=hi; BL[br*GBN+bc+3]=lo;
            h_split(rb1.x,hi,lo); BH[br*GBN+bc+64]=hi; BL[br*GBN+bc+64]=lo;
            h_split(rb1.y,hi,lo); BH[br*GBN+bc+65]=hi; BL[br*GBN+bc+65]=lo;
            h_split(rb1.z,hi,lo); BH[br*GBN+bc+66]=hi; BL[br*GBN+bc+66]=lo;
            h_split(rb1.w,hi,lo); BH[br*GBN+bc+67]=hi; BL[br*GBN+bc+67]=lo;
        }
        __syncthreads();
    }

    // ---------------- epilogue: per-warp smem staging, two 32-col passes ----
    float* stg = fs + wid*1152;               // 32x36 floats per warp
    #pragma unroll
    for (int p=0;p<2;p++){
        __syncwarp();
        #pragma unroll
        for (int i=0;i<2;i++)
            #pragma unroll
            for (int j=0;j<2;j++)
                wmma::store_matrix_sync(stg + i*16*36 + j*16, acc[i][p*2+j], 36, wmma::mem_row_major);
        __syncwarp();
        #pragma unroll
        for (int t=0;t<8;t++){
            int idx = lid + t*32;             // 256 float4 per warp (32x32)
            int r = idx>>3, c4 = idx&7;
            int gr = tile_m + wm*32 + r;
            int gc = tile_n + wn*64 + p*32 + c4*4;
            float4 v = *(const float4*)(stg + r*36 + c4*4);
            if (bias){
                float4 bb = *(const float4*)(bias + gc);
                v.x+=bb.x; v.y+=bb.y; v.z+=bb.z; v.w+=bb.w;
            }
            if (rowscale){
                float rs = rowscale[gr];
                float4 cv = *(const float4*)(colvec + gc);
                float4 cb = *(const float4*)(colbias + gc);
                v.x += rs*cv.x + cb.x; v.y += rs*cv.y + cb.y;
                v.z += rs*cv.z + cb.z; v.w += rs*cv.w + cb.w;
            }
            if (gelu){
                v.x = 0.5f*v.x*(1.f + erff(v.x*0.70710678118f));
                v.y = 0.5f*v.y*(1.f + erff(v.y*0.70710678118f));
                v.z = 0.5f*v.z*(1.f + erff(v.z*0.70710678118f));
                v.w = 0.5f*v.w*(1.f + erff(v.w*0.70710678118f));
            }
            if (residual){
                float4 rr = *(const float4*)(residual + (size_t)gr*N + gc);
                v.x+=rr.x; v.y+=rr.y; v.z+=rr.z; v.w+=rr.w;
            }
            *(float4*)(C + (size_t)gr*N + gc) = v;
        }
    }
}

// ======================================================================
// Fused flash attention: rope(Q)·rope(K)^T -> mask -> softmax -> ·V
// One CTA per (q-tile 64, b, h). 256 threads, 8 warps.
// Dynamic smem layout (bytes):
//   [0,131072)        scores fp32 [64][512]  (later reused as out staging [64][72])
//   [131072,149504)   Qh/Ql [64][72] halves   (later reused as Ph/Pl)
//   [149504,186368)   Kh/Kl [128][72] halves  (later reused as Vh/Vl [64][72])
//   [186368,188416)   mask bias fp32 [512]
// ======================================================================
#define FA_SMEM 188416

__global__ __launch_bounds__(256) void k_flash(
    const float* __restrict__ qb,
    const float* __restrict__ kb,
    const float* __restrict__ vb,
    const int* __restrict__ mask,
    const float* __restrict__ rope,
    float* __restrict__ at)
{
    extern __shared__ __align__(16) unsigned char dsm[];
    float* sc = (float*)dsm;                       // [64][512]
    half*  Qh = (half*)(dsm + 131072);             // [64][72]
    half*  Ql = Qh + 64*72;
    half*  Kh = (half*)(dsm + 149504);             // [128][72]
    half*  Kl = Kh + 128*72;
    float* mb = (float*)(dsm + 186368);            // [512]

    int tid = threadIdx.x, wid = tid>>5, lane = tid&31;
    int qt = blockIdx.x, bh = blockIdx.y;
    int b = bh >> 4, h = bh & 15;

    // mask bias
    #pragma unroll
    for (int t=0;t<2;t++){
        int c = tid + t*256;
        mb[c] = mask[b*SQ + c] ? -1e30f : 0.f;
    }

    // load Q tile with rope + split: 64 rows x 32 pairs
    #pragma unroll
    for (int t=0;t<8;t++){
        int idx = tid + t*256;
        int r = idx>>5, j = idx&31;
        int s = qt*64 + r;
        size_t base = ((size_t)s*BB + b)*DD + h*HDIM;
        float a1 = qb[base+j], a2 = qb[base+j+32];
        float c  = rope[(s*32+j)*2], sn = rope[(s*32+j)*2+1];
        float o1 = a1*c - a2*sn;
        float o2 = a2*c + a1*sn;
        half hi,lo;
        h_split(o1,hi,lo); Qh[r*72+j]=hi;    Ql[r*72+j]=lo;
        h_split(o2,hi,lo); Qh[r*72+j+32]=hi; Ql[r*72+j+32]=lo;
    }
    __syncthreads();

    // ---- scores phase: 4 slabs of 128 keys ----
    int wm = wid&1, wn = wid>>1;   // 2 x 4 warps
    for (int ks=0; ks<4; ks++){
        // load 128 K rows with rope + split
        #pragma unroll
        for (int t=0;t<16;t++){
            int idx = tid + t*256;
            int r = idx>>5, j = idx&31;
            int sk = ks*128 + r;
            size_t base = ((size_t)sk*BB + b)*DD + h*HDIM;
            float a1 = kb[base+j], a2 = kb[base+j+32];
            float c  = rope[(sk*32+j)*2], sn = rope[(sk*32+j)*2+1];
            float o1 = a1*c - a2*sn;
            float o2 = a2*c + a1*sn;
            half hi,lo;
            h_split(o1,hi,lo); Kh[r*72+j]=hi;    Kl[r*72+j]=lo;
            h_split(o2,hi,lo); Kh[r*72+j+32]=hi; Kl[r*72+j+32]=lo;
        }
        __syncthreads();
        // MMA: warp computes 32x32 strip (rows wm*32, cols wn*32 within slab)
        wmma::fragment<wmma::accumulator,16,16,16,float> acc[2][2];
        #pragma unroll
        for (int i=0;i<2;i++)
            #pragma unroll
            for (int j=0;j<2;j++) wmma::fill_fragment(acc[i][j], 0.f);
        #pragma unroll
        for (int kk=0; kk<64; kk+=16){
            wmma::fragment<wmma::matrix_a,16,16,16,half,wmma::row_major> ah[2], al[2];
            wmma::fragment<wmma::matrix_b,16,16,16,half,wmma::col_major> bh[2], bl[2];
            #pragma unroll
            for (int i=0;i<2;i++){
                wmma::load_matrix_sync(ah[i], Qh + (wm*32+i*16)*72 + kk, 72);
                wmma::load_matrix_sync(al[i], Ql + (wm*32+i*16)*72 + kk, 72);
                wmma::load_matrix_sync(bh[i], Kh + (wn*32+i*16)*72 + kk, 72);
                wmma::load_matrix_sync(bl[i], Kl + (wn*32+i*16)*72 + kk, 72);
            }
            #pragma unroll
            for (int i=0;i<2;i++)
                #pragma unroll
                for (int j=0;j<2;j++){
                    wmma::mma_sync(acc[i][j], ah[i], bl[j], acc[i][j]);
                    wmma::mma_sync(acc[i][j], al[i], bh[j], acc[i][j]);
                    wmma::mma_sync(acc[i][j], ah[i], bh[j], acc[i][j]);
                }
        }
        #pragma unroll
        for (int i=0;i<2;i++)
            #pragma unroll
            for (int j=0;j<2;j++)
                wmma::store_matrix_sync(sc + (wm*32+i*16)*512 + ks*128 + wn*32 + j*16,
                                        acc[i][j], 512, wmma::mem_row_major);
        __syncthreads();
    }

    // ---- softmax: each warp owns 8 rows ----
    {
        int r0 = wid*8;
        for (int rr=0; rr<8; rr++){
            int r = r0 + rr;
            float v[16];
            float m = -3.4e38f;
            #pragma unroll
            for (int k2=0;k2<16;k2++){
                int c = lane + k2*32;
                v[k2] = sc[r*512+c]*0.125f + mb[c];
                m = fmaxf(m, v[k2]);
            }
            #pragma unroll
            for (int o=16;o;o>>=1) m = fmaxf(m, __shfl_xor_sync(0xffffffffu,m,o));
            float s = 0.f;
            #pragma unroll
            for (int k2=0;k2<16;k2++){ v[k2] = expf(v[k2]-m); s += v[k2]; }
            #pragma unroll
            for (int o=16;o;o>>=1) s += __shfl_xor_sync(0xffffffffu,s,o);
            float inv = 1.f/s;
            #pragma unroll
            for (int k2=0;k2<16;k2++) sc[r*512 + lane + k2*32] = v[k2]*inv;
        }
    }
    __syncthreads();

    // ---- PV phase: stream V in 8 chunks of 64 keys; P reuses Q buf, V reuses K buf
    half* Ph = Qh; half* Pl = Ql;
    half* Vh = Kh; half* Vl = Kl;
    wmma::fragment<wmma::accumulator,16,16,16,float> oacc[2];
    wmma::fill_fragment(oacc[0], 0.f);
    wmma::fill_fragment(oacc[1], 0.f);
    int pn = wid>>1;   // 4 col strips of 16
    for (int kc=0; kc<8; kc++){
        // convert P chunk 64x64 to fp16 split
        #pragma unroll
        for (int t=0;t<16;t++){
            int idx = tid + t*256;
            int r = idx>>6, c = idx&63;
            half hi,lo;
            h_split(sc[r*512 + kc*64 + c], hi, lo);
            Ph[r*72+c]=hi; Pl[r*72+c]=lo;
        }
        // load V chunk 64x64
        #pragma unroll
        for (int t=0;t<4;t++){
            int idx = tid + t*256;
            int r = idx>>4, c = (idx&15)*4;
            float4 v = *(const float4*)(vb + ((size_t)(kc*64+r)*BB + b)*DD + h*HDIM + c);
            half hi,lo;
            h_split(v.x,hi,lo); Vh[r*72+c+0]=hi; Vl[r*72+c+0]=lo;
            h_split(v.y,hi,lo); Vh[r*72+c+1]=hi; Vl[r*72+c+1]=lo;
            h_split(v.z,hi,lo); Vh[r*72+c+2]=hi; Vl[r*72+c+2]=lo;
            h_split(v.w,hi,lo); Vh[r*72+c+3]=hi; Vl[r*72+c+3]=lo;
        }
        __syncthreads();
        #pragma unroll
        for (int kk=0; kk<64; kk+=16){
            wmma::fragment<wmma::matrix_a,16,16,16,half,wmma::row_major> ah[2], al[2];
            wmma::fragment<wmma::matrix_b,16,16,16,half,wmma::row_major> bh, bl;
            #pragma unroll
            for (int i=0;i<2;i++){
                wmma::load_matrix_sync(ah[i], Ph + (wm*32+i*16)*72 + kk, 72);
                wmma::load_matrix_sync(al[i], Pl + (wm*32+i*16)*72 + kk, 72);
            }
            wmma::load_matrix_sync(bh, Vh + kk*72 + pn*16, 72);
            wmma::load_matrix_sync(bl, Vl + kk*72 + pn*16, 72);
            #pragma unroll
            for (int i=0;i<2;i++){
                wmma::mma_sync(oacc[i], ah[i], bl, oacc[i]);
                wmma::mma_sync(oacc[i], al[i], bh, oacc[i]);
                wmma::mma_sync(oacc[i], ah[i], bh, oacc[i]);
            }
        }
        __syncthreads();
    }

    // stage output 64x64 (stride 72) in sc region, then coalesced write
    float* ost = sc;
    #pragma unroll
    for (int i=0;i<2;i++)
        wmma::store_matrix_sync(ost + (wm*32+i*16)*72 + pn*16, oacc[i], 72, wmma::mem_row_major);
    __syncthreads();
    #pragma unroll
    for (int t=0;t<4;t++){
        int idx = tid + t*256;
        int r = idx>>4, c = (idx&15)*4;
        float4 v = *(const float4*)(ost + r*72 + c);
        *(float4*)(at + ((size_t)(qt*64+r)*BB + b)*DD + h*HDIM + c) = v;
    }
}

// ---------------- host ----------------
extern "C" void kernel_launch(void* const* d_in, const int* in_sizes, int n_in,
                              void* d_out, int out_size){
    const float* segments  = (const float*)d_in[0];
    const float* durations = (const float*)d_in[1];
    const unsigned char* maskraw = (const unsigned char*)d_in[2];
    const float* Wproj = (const float*)d_in[3];
    const float* bproj = (const float*)d_in[4];
    const float* Wdur  = (const float*)d_in[5];
    const float* bdur  = (const float*)d_in[6];
    const float* ln1g  = (const float*)d_in[7];
    const float* ln1b  = (const float*)d_in[8];
    const float* Wq    = (const float*)d_in[9];
    const float* bq    = (const float*)d_in[10];
    const float* Wk    = (const float*)d_in[11];
    const float* bk    = (const float*)d_in[12];
    const float* Wv    = (const float*)d_in[13];
    const float* bv    = (const float*)d_in[14];
    const float* Wo    = (const float*)d_in[15];
    const float* bo    = (const float*)d_in[16];
    const float* ln2g  = (const float*)d_in[17];
    const float* ln2b  = (const float*)d_in[18];
    const float* W1    = (const float*)d_in[19];
    const float* b1    = (const float*)d_in[20];
    const float* W2    = (const float*)d_in[21];
    const float* b2    = (const float*)d_in[22];

    float *px,*ph,*pq,*pk,*pv,*pat,*pfh,*prc;
    int* pmask;
    cudaGetSymbolAddress((void**)&px,  g_x);
    cudaGetSymbolAddress((void**)&ph,  g_h);
    cudaGetSymbolAddress((void**)&pq,  g_q);
    cudaGetSymbolAddress((void**)&pk,  g_k);
    cudaGetSymbolAddress((void**)&pv,  g_v);
    cudaGetSymbolAddress((void**)&pat, g_attn);
    cudaGetSymbolAddress((void**)&pfh, g_ffh);
    cudaGetSymbolAddress((void**)&prc, g_rope);
    cudaGetSymbolAddress((void**)&pmask, g_mask);

    cudaFuncSetAttribute(k_flash, cudaFuncAttributeMaxDynamicSharedMemorySize, FA_SMEM);

    k_mask_prep<<<1,256>>>(maskraw, pmask);
    k_rope_cache<<<64,256>>>(prc);

    // x = segments@Wproj + bproj + dur*Wdur + bdur
    k_gemm<<<dim3(8,16),256>>>(segments, DIN_, Wproj, bproj, nullptr,
                                durations, Wdur, bdur, px, DD, DIN_, 0);

    for (int l=0; l<LAYERS; l++){
        size_t wdd = (size_t)l*DD*DD;
        k_ln<<<MROWS,256>>>(px, ln1g + l*DD, ln1b + l*DD, ph);

        k_gemm<<<dim3(8,16),256>>>(ph, DD, Wq + wdd, bq + l*DD, nullptr,
                                    nullptr,nullptr,nullptr, pq, DD, DD, 0);
        k_gemm<<<dim3(8,16),256>>>(ph, DD, Wk + wdd, bk + l*DD, nullptr,
                                    nullptr,nullptr,nullptr, pk, DD, DD, 0);
        k_gemm<<<dim3(8,16),256>>>(ph, DD, Wv + wdd, bv + l*DD, nullptr,
                                    nullptr,nullptr,nullptr, pv, DD, DD, 0);

        // fused rope + scores + mask + softmax + PV
        k_flash<<<dim3(8,BB*HH),256,FA_SMEM>>>(pq, pk, pv, pmask, prc, pat);

        // x = x + attn@Wo + bo
        k_gemm<<<dim3(8,16),256>>>(pat, DD, Wo + wdd, bo + l*DD, px,
                                    nullptr,nullptr,nullptr, px, DD, DD, 0);

        k_ln<<<MROWS,256>>>(px, ln2g + l*DD, ln2b + l*DD, ph);

        // ffh = gelu(h@W1 + b1)
        k_gemm<<<dim3(32,16),256>>>(ph, DD, W1 + (size_t)l*DD*FF_, b1 + l*FF_, nullptr,
                                    nullptr,nullptr,nullptr, pfh, FF_, DD, 1);

        // x = x + ffh@W2 + b2   (last layer writes straight into d_out)
        float* outp = (l == LAYERS-1) ? (float*)d_out : px;
        k_gemm<<<dim3(8,16),256>>>(pfh, FF_, W2 + (size_t)l*FF_*DD, b2 + l*DD, px,
                                    nullptr,nullptr,nullptr, outp, DD, FF_, 0);
    }
}